// round 6
// baseline (speedup 1.0000x reference)
#include <cuda_runtime.h>
#include <cstdint>

#define MM   6
#define BB   128
#define TT   32
#define DINN 64
#define HHH  512
#define EEE  512
#define NEMB 32

#define MAXC      80     // max chunks: (128 + 32)/2
#define ROWS      64     // token rows per block: 2 batches x 32
#define XS_STRIDE 68     // words; mod 32 = 4 -> conflict-free A-fragment LDS
#define HS_STRIDE 516    // words; mod 32 = 4
#define WB_STRIDE 520    // words; mod 32 = 8 -> conflict-free B-fragment LDS
#define SLAB_WORDS (8 * WB_STRIDE)   // one 8k x 512n slab (padded)

// smem word offsets
#define XS_OFF 0
#define HS_OFF (ROWS * XS_STRIDE)                    // 4352
#define WB_OFF (HS_OFF + ROWS * HS_STRIDE)           // 37376
#define SMEM_WORDS (WB_OFF + 2 * SLAB_WORDS)         // 45696 -> 182784 B

// chunk table: (b0, b1) pairs sharing one emb id, grouped by emb
__device__ int g_chunk_b0[MAXC];
__device__ int g_chunk_b1[MAXC];
__device__ int g_chunk_e [MAXC];
__device__ int g_nchunks;

__global__ void pmst_prepass(const int* __restrict__ emb_ids) {
    const int e = threadIdx.x;             // 0..31
    int cnt = 0;
    for (int b = 0; b < BB; b++) cnt += (emb_ids[b] == e);
    int pairs = (cnt + 1) >> 1;
    int off = pairs;
    #pragma unroll
    for (int d = 1; d < 32; d <<= 1) {
        int v = __shfl_up_sync(0xFFFFFFFFu, off, d);
        if (e >= d) off += v;
    }
    if (e == 31) g_nchunks = off;
    int idx = off - pairs;
    int prev = -1;
    for (int b = 0; b < BB; b++) {
        if (emb_ids[b] == e) {
            if (prev < 0) prev = b;
            else { g_chunk_b0[idx] = prev; g_chunk_b1[idx] = b; g_chunk_e[idx] = e; idx++; prev = -1; }
        }
    }
    if (prev >= 0) { g_chunk_b0[idx] = prev; g_chunk_b1[idx] = prev; g_chunk_e[idx] = e; }
}

__device__ __forceinline__ uint32_t f2tf(float f) {
    uint32_t r; asm("cvt.rna.tf32.f32 %0, %1;" : "=r"(r) : "f"(f)); return r;
}

__device__ __forceinline__ void mma8(float* d, const uint32_t* a, const uint32_t* b) {
    asm volatile(
        "mma.sync.aligned.m16n8k8.row.col.f32.tf32.tf32.f32 "
        "{%0,%1,%2,%3}, {%4,%5,%6,%7}, {%8,%9}, {%0,%1,%2,%3};"
        : "+f"(d[0]), "+f"(d[1]), "+f"(d[2]), "+f"(d[3])
        : "r"(a[0]), "r"(a[1]), "r"(a[2]), "r"(a[3]), "r"(b[0]), "r"(b[1]));
}

// Load one 8k x 512n weight slab into registers (coalesced LDG.128).
__device__ __forceinline__ void ldg_slab(const float* __restrict__ wp, uint4* st, int tid) {
    #pragma unroll
    for (int j = 0; j < 4; j++) {
        const int i = tid + j * 256;
        const int row = i >> 7, c4 = i & 127;
        st[j] = *(const uint4*)(wp + (long)row * 512 + c4 * 4);
    }
}
// Convert to tf32 and store slab (STS.128, conflict-free).
__device__ __forceinline__ void sts_slab(uint32_t* buf, const uint4* st, int tid) {
    #pragma unroll
    for (int j = 0; j < 4; j++) {
        const int i = tid + j * 256;
        const int row = i >> 7, c4 = i & 127;
        uint4 v;
        v.x = f2tf(__uint_as_float(st[j].x));
        v.y = f2tf(__uint_as_float(st[j].y));
        v.z = f2tf(__uint_as_float(st[j].z));
        v.w = f2tf(__uint_as_float(st[j].w));
        *(uint4*)(buf + row * WB_STRIDE + c4 * 4) = v;
    }
}

// grid = (MAXC, MM); block = 256 threads (8 warps). Warp tile: 64 rows x 64 cols.
__global__ __launch_bounds__(256, 1) void pmst_mma_kernel(
    const float* __restrict__ state,   // [B, T, M*DIN]
    const float* __restrict__ W1,      // [M, NEMB, DIN, H]
    const float* __restrict__ b1,      // [M, NEMB, H]
    const float* __restrict__ W2,      // [M, NEMB, H, E]
    const float* __restrict__ b2,      // [M, NEMB, E]
    const float* __restrict__ te,      // [M, E]
    float* __restrict__ out)           // [B, M*T, E]
{
    const int c = blockIdx.x;
    if (c >= g_nchunks) return;
    const int m   = blockIdx.y;
    const int e   = g_chunk_e[c];
    const int b0  = g_chunk_b0[c];
    const int b1v = g_chunk_b1[c];

    extern __shared__ uint32_t smu[];
    uint32_t* Xs = smu + XS_OFF;
    uint32_t* Hs = smu + HS_OFF;
    uint32_t* Wb = smu + WB_OFF;

    const int tid  = threadIdx.x;
    const int wid  = tid >> 5;
    const int lane = tid & 31;
    const int g    = lane >> 2;    // 0..7
    const int tg   = lane & 3;     // 0..3

    const long me = (long)m * NEMB + e;
    const float* W1p = W1 + me * (DINN * HHH);
    const float* W2p = W2 + me * ((long)HHH * EEE);
    const float* b1p = b1 + me * HHH;
    const float* b2p = b2 + me * EEE;
    const float* tep = te + (long)m * EEE;

    const int ncol0 = wid * 64;
    uint4 st[4];
    float acc[4][8][4];   // [m-tile 16 rows][n-tile 8 cols][frag]

    // ---- preload W1 slab 0, stage X, store slab ----
    ldg_slab(W1p, st, tid);
    {
        #pragma unroll
        for (int i = tid; i < ROWS * DINN; i += 256) {
            const int tr = i >> 6, k = i & 63;
            const int bb = (tr < TT) ? b0 : b1v;
            const int t  = tr & (TT - 1);
            Xs[tr * XS_STRIDE + k] =
                f2tf(__ldg(state + ((long)bb * TT + t) * (MM * DINN) + m * DINN + k));
        }
    }
    sts_slab(Wb, st, tid);
    __syncthreads();

    // ================= GEMM1: H = relu(X @ W1 + b1) =================
    #pragma unroll
    for (int mt = 0; mt < 4; mt++)
        #pragma unroll
        for (int nt = 0; nt < 8; nt++)
            #pragma unroll
            for (int i = 0; i < 4; i++) acc[mt][nt][i] = 0.f;

    for (int kc = 0; kc < 8; kc++) {
        if (kc < 7) ldg_slab(W1p + (long)(kc + 1) * 8 * 512, st, tid);
        const uint32_t* wbuf = Wb + (kc & 1) * SLAB_WORDS;
        uint32_t a[4][4];
        {
            const uint32_t* xb = Xs + g * XS_STRIDE + tg + kc * 8;
            #pragma unroll
            for (int mt = 0; mt < 4; mt++) {
                const uint32_t* xp = xb + mt * 16 * XS_STRIDE;
                a[mt][0] = xp[0];
                a[mt][1] = xp[8 * XS_STRIDE];
                a[mt][2] = xp[4];
                a[mt][3] = xp[8 * XS_STRIDE + 4];
            }
        }
        const uint32_t* wf = wbuf + tg * WB_STRIDE + ncol0 + g;
        #pragma unroll
        for (int nt = 0; nt < 8; nt++) {
            uint32_t bf[2];
            bf[0] = wf[nt * 8];
            bf[1] = wf[4 * WB_STRIDE + nt * 8];
            #pragma unroll
            for (int mt = 0; mt < 4; mt++) mma8(acc[mt][nt], a[mt], bf);
        }
        if (kc < 7) sts_slab(Wb + ((kc + 1) & 1) * SLAB_WORDS, st, tid);
        __syncthreads();
    }

    // ---- preload W2 slab 0; epilogue1: relu + bias -> Hs ----
    ldg_slab(W2p, st, tid);
    #pragma unroll
    for (int nt = 0; nt < 8; nt++) {
        const int n = ncol0 + nt * 8 + tg * 2;
        const float bb0 = __ldg(b1p + n);
        const float bb1 = __ldg(b1p + n + 1);
        #pragma unroll
        for (int mt = 0; mt < 4; mt++) {
            const int r0 = mt * 16 + g;
            Hs[r0 * HS_STRIDE + n]           = f2tf(fmaxf(acc[mt][nt][0] + bb0, 0.f));
            Hs[r0 * HS_STRIDE + n + 1]       = f2tf(fmaxf(acc[mt][nt][1] + bb1, 0.f));
            Hs[(r0 + 8) * HS_STRIDE + n]     = f2tf(fmaxf(acc[mt][nt][2] + bb0, 0.f));
            Hs[(r0 + 8) * HS_STRIDE + n + 1] = f2tf(fmaxf(acc[mt][nt][3] + bb1, 0.f));
        }
    }
    sts_slab(Wb, st, tid);
    __syncthreads();

    // ================= GEMM2: Z = H @ W2 + b2 + te =================
    #pragma unroll
    for (int mt = 0; mt < 4; mt++)
        #pragma unroll
        for (int nt = 0; nt < 8; nt++)
            #pragma unroll
            for (int i = 0; i < 4; i++) acc[mt][nt][i] = 0.f;

    for (int kc = 0; kc < 64; kc++) {
        if (kc < 63) ldg_slab(W2p + (long)(kc + 1) * 8 * 512, st, tid);
        const uint32_t* wbuf = Wb + (kc & 1) * SLAB_WORDS;
        uint32_t a[4][4];
        {
            const uint32_t* hb = Hs + g * HS_STRIDE + tg + kc * 8;
            #pragma unroll
            for (int mt = 0; mt < 4; mt++) {
                const uint32_t* hp = hb + mt * 16 * HS_STRIDE;
                a[mt][0] = hp[0];
                a[mt][1] = hp[8 * HS_STRIDE];
                a[mt][2] = hp[4];
                a[mt][3] = hp[8 * HS_STRIDE + 4];
            }
        }
        const uint32_t* wf = wbuf + tg * WB_STRIDE + ncol0 + g;
        #pragma unroll
        for (int nt = 0; nt < 8; nt++) {
            uint32_t bf[2];
            bf[0] = wf[nt * 8];
            bf[1] = wf[4 * WB_STRIDE + nt * 8];
            #pragma unroll
            for (int mt = 0; mt < 4; mt++) mma8(acc[mt][nt], a[mt], bf);
        }
        if (kc < 63) sts_slab(Wb + ((kc + 1) & 1) * SLAB_WORDS, st, tid);
        __syncthreads();
    }

    // ---- Epilogue2: out[b, m*T + t, o] ----
    {
        float* op0 = out + ((long)b0  * MM + m) * TT * EEE;
        float* op1 = out + ((long)b1v * MM + m) * TT * EEE;
        #pragma unroll
        for (int nt = 0; nt < 8; nt++) {
            const int n = ncol0 + nt * 8 + tg * 2;
            const float a0 = __ldg(b2p + n)     + __ldg(tep + n);
            const float a1 = __ldg(b2p + n + 1) + __ldg(tep + n + 1);
            #pragma unroll
            for (int mt = 0; mt < 4; mt++) {
                const int r0 = mt * 16 + g;        // row in [0,64)
                const int r1 = r0 + 8;
                float* p0 = ((r0 < TT) ? op0 : op1) + (long)(r0 & (TT - 1)) * EEE + n;
                float* p1 = ((r1 < TT) ? op0 : op1) + (long)(r1 & (TT - 1)) * EEE + n;
                *(float2*)p0 = make_float2(acc[mt][nt][0] + a0, acc[mt][nt][1] + a1);
                *(float2*)p1 = make_float2(acc[mt][nt][2] + a0, acc[mt][nt][3] + a1);
            }
        }
    }
}

extern "C" void kernel_launch(void* const* d_in, const int* in_sizes, int n_in,
                              void* d_out, int out_size)
{
    const float* state   = (const float*)d_in[0];
    const int*   emb_ids = (const int*)  d_in[1];
    const float* W1      = (const float*)d_in[2];
    const float* b1      = (const float*)d_in[3];
    const float* W2      = (const float*)d_in[4];
    const float* b2      = (const float*)d_in[5];
    const float* te      = (const float*)d_in[6];
    float*       out     = (float*)d_out;

    pmst_prepass<<<1, 32>>>(emb_ids);

    const int smem_bytes = SMEM_WORDS * (int)sizeof(uint32_t); // 182784
    cudaFuncSetAttribute(pmst_mma_kernel,
                         cudaFuncAttributeMaxDynamicSharedMemorySize, smem_bytes);

    dim3 grid(MAXC, MM);
    pmst_mma_kernel<<<grid, 256, smem_bytes>>>(state, W1, b1, W2, b2, te, out);
}